// round 4
// baseline (speedup 1.0000x reference)
#include <cuda_runtime.h>
#include <cuda_bf16.h>
#include <math.h>

// Problem constants
#define BATCH   64
#define NF      256
#define WIN     128
#define EMB     128
#define TOPK    32
#define ALPHA   0.2f

// Scratch
__device__ float g_Wx[BATCH * NF * EMB];   // Wx = x_n @ W_n + b_n  (8.4 MB)
__device__ float g_d1[BATCH * NF];         // dot(Wx[b,r], a[:128])
__device__ float g_d2[BATCH * NF];         // dot(Wx[b,r], a[128:])

__device__ __forceinline__ float lrelu(float v) {
    return fmaxf(v, ALPHA * v);   // valid for alpha in (0,1)
}

// ---------------------------------------------------------------------------
// Kernel 1: GEMM  Wx[r][e] = sum_w x[r][w]*W[w][e] + b[e], fused d1/d2.
// M = 16384, K = 128, N = 128.  512 blocks x 32 rows, 256 thr, 2x8 microtile
// (low regs -> high occupancy; GEMM was latency-bound at 256 blocks).
// ---------------------------------------------------------------------------
__global__ __launch_bounds__(256) void gemm_wx_kernel(
    const float* __restrict__ x,   // [BATCH*NF, WIN]
    const float* __restrict__ Wn,  // [WIN, EMB]
    const float* __restrict__ bn,  // [EMB]
    const float* __restrict__ a)   // [2*EMB]
{
    __shared__ float sX[32][33];    // [k][m] (32 rows), padded
    __shared__ float sW[32][128];   // [k][e]

    const int t    = threadIdx.x;
    const int row0 = blockIdx.x * 32;
    const int tx   = t & 15;       // e-direction
    const int ty   = t >> 4;       // m-direction (16 values)

    float acc[2][8];
#pragma unroll
    for (int i = 0; i < 2; i++)
#pragma unroll
        for (int j = 0; j < 8; j++) acc[i][j] = 0.0f;

    for (int kt = 0; kt < WIN; kt += 32) {
        // X tile: 32 rows x 32 k, transposed into sX[k][m]. 4 elems/thread.
#pragma unroll
        for (int i = 0; i < 4; i++) {
            int idx = t + i * 256;
            int m = idx >> 5, w = idx & 31;
            sX[w][m] = x[(size_t)(row0 + m) * WIN + kt + w];
        }
        // W tile: 32 k x 128 e. 16 elems/thread.
#pragma unroll
        for (int i = 0; i < 16; i++) {
            int idx = t + i * 256;
            int kk = idx >> 7, e = idx & 127;
            sW[kk][e] = Wn[(size_t)(kt + kk) * EMB + e];
        }
        __syncthreads();

#pragma unroll
        for (int kk = 0; kk < 32; kk++) {
            float ra[2], rb[8];
#pragma unroll
            for (int i = 0; i < 2; i++) ra[i] = sX[kk][ty + 16 * i];
#pragma unroll
            for (int j = 0; j < 8; j++) rb[j] = sW[kk][tx + 16 * j];
#pragma unroll
            for (int i = 0; i < 2; i++)
#pragma unroll
                for (int j = 0; j < 8; j++)
                    acc[i][j] = fmaf(ra[i], rb[j], acc[i][j]);
        }
        __syncthreads();
    }

    // Epilogue: bias, store Wx, fused projections d1/d2
    float a1v[8], a2v[8], bnv[8];
#pragma unroll
    for (int j = 0; j < 8; j++) {
        int e = tx + 16 * j;
        a1v[j] = __ldg(a + e);
        a2v[j] = __ldg(a + EMB + e);
        bnv[j] = __ldg(bn + e);
    }
    float p1[2] = {0, 0};
    float p2[2] = {0, 0};
#pragma unroll
    for (int i = 0; i < 2; i++) {
        int m = row0 + ty + 16 * i;
#pragma unroll
        for (int j = 0; j < 8; j++) {
            int e = tx + 16 * j;
            float val = acc[i][j] + bnv[j];
            g_Wx[(size_t)m * EMB + e] = val;
            p1[i] = fmaf(val, a1v[j], p1[i]);
            p2[i] = fmaf(val, a2v[j], p2[i]);
        }
    }
    // Reduce across the 16 tx lanes (same ty within half-warp)
#pragma unroll
    for (int i = 0; i < 2; i++) {
#pragma unroll
        for (int o = 8; o > 0; o >>= 1) {
            p1[i] += __shfl_xor_sync(0xffffffffu, p1[i], o);
            p2[i] += __shfl_xor_sync(0xffffffffu, p2[i], o);
        }
    }
    if (tx == 0) {
#pragma unroll
        for (int i = 0; i < 2; i++) {
            int m = row0 + ty + 16 * i;
            g_d1[m] = p1[i];
            g_d2[m] = p2[i];
        }
    }
}

// ---------------------------------------------------------------------------
// Kernel 2: warp-autonomous attention + streaming output. One warp per (b,n).
// Gather loads via __ldcg (L2-only; they're L2-hits, keep them out of L1).
// ---------------------------------------------------------------------------
__global__ __launch_bounds__(256) void attn_stream_kernel(
    const int*   __restrict__ edge,   // [2, NF*TOPK] (row 0 used)
    const float* __restrict__ bias,   // [NF, TOPK]
    float*       __restrict__ out)    // [BATCH, NF, TOPK, EMB]
{
    const int gw = (blockIdx.x * blockDim.x + threadIdx.x) >> 5;  // (b,n)
    const int l  = threadIdx.x & 31;
    const int b  = gw >> 8;           // NF = 256
    const int n  = gw & 255;

    const float* d1 = g_d1 + b * NF;
    const float* d2 = g_d2 + b * NF;

    const int nbr_l = __ldg(edge + n * TOPK + l);

    // Score for lane l
    float score;
    if (l < 16) {
        score = lrelu(d1[n] + d2[n]);
    } else {
        int j0 = 2 * l - 32;
        int n0 = __ldg(edge + n * TOPK + j0);
        int n1 = __ldg(edge + n * TOPK + j0 + 1);
        score = lrelu(d1[n0] + d2[n1]);
    }
    float bv = __ldg(bias + n * TOPK + l);
    if (isnan(bv)) bv = 0.0f;
    else if (isinf(bv)) bv = bv > 0.0f ? 3.4028235e38f : -3.4028235e38f;
    score += bv;

    // Warp softmax over 32 lanes
    float m = score;
#pragma unroll
    for (int o = 16; o > 0; o >>= 1) m = fmaxf(m, __shfl_xor_sync(0xffffffffu, m, o));
    float ex = __expf(score - m);
    float s = ex;
#pragma unroll
    for (int o = 16; o > 0; o >>= 1) s += __shfl_xor_sync(0xffffffffu, s, o);
    const float att = ex / s;

    // Streaming output: 32 rows x 32 float4 (lane = float4 index within row)
    const float* wxb = g_Wx + (size_t)b * NF * EMB;
    float4* outp = (float4*)(out + (size_t)gw * TOPK * EMB);

#pragma unroll 8
    for (int k = 0; k < TOPK; k++) {
        int   nb = __shfl_sync(0xffffffffu, nbr_l, k);
        float ak = __shfl_sync(0xffffffffu, att,   k);
        const float4* src = (const float4*)(wxb + (size_t)nb * EMB);
        float4 v = __ldcg(src + l);          // bypass L1, L2-hit
        v.x = lrelu(v.x) * ak;
        v.y = lrelu(v.y) * ak;
        v.z = lrelu(v.z) * ak;
        v.w = lrelu(v.w) * ak;
        __stcs(outp + k * 32 + l, v);
    }
}

// ---------------------------------------------------------------------------
// Launch. Inputs: 0:x_n 1:x_e 2:edge_indices 3:all_embeddings 4:W_n 5:b_n
//                 6:a 7:bias_n   (x_e, all_embeddings unused)
// ---------------------------------------------------------------------------
extern "C" void kernel_launch(void* const* d_in, const int* in_sizes, int n_in,
                              void* d_out, int out_size) {
    const float* x_n  = (const float*)d_in[0];
    const int*   edge = (const int*)  d_in[2];
    const float* W_n  = (const float*)d_in[4];
    const float* b_n  = (const float*)d_in[5];
    const float* a    = (const float*)d_in[6];
    const float* bias = (const float*)d_in[7];
    float* out = (float*)d_out;

    gemm_wx_kernel<<<(BATCH * NF) / 32, 256>>>(x_n, W_n, b_n, a);
    attn_stream_kernel<<<(BATCH * NF * 32) / 256, 256>>>(edge, bias, out);
}

// round 5
// speedup vs baseline: 1.1232x; 1.1232x over previous
#include <cuda_runtime.h>
#include <cuda_bf16.h>
#include <math.h>

// Problem constants
#define BATCH   64
#define NF      256
#define WIN     128
#define EMB     128
#define TOPK    32
#define ALPHA   0.2f

#define GEMM_BLK  256     // 64-row tiles
#define ATTN_BLK  2048    // 8 warps each, one warp per (b,n)

// Scratch
__device__ float    g_Wx[BATCH * NF * EMB];   // Wx = x_n @ W_n + b_n  (8.4 MB)
__device__ float    g_d1[BATCH * NF];         // dot(Wx[b,r], a[:128])
__device__ float    g_d2[BATCH * NF];         // dot(Wx[b,r], a[128:])
__device__ unsigned g_flag[BATCH];            // per-batch tiles-done (0..4)
__device__ unsigned g_done;                   // attn blocks finished (self-reset)

__device__ __forceinline__ float lrelu(float v) {
    return fmaxf(v, ALPHA * v);   // valid for alpha in (0,1)
}

// ---------------------------------------------------------------------------
// Kernel 1 (PDL primary): GEMM Wx = x@W + b, fused d1/d2 epilogue,
// per-batch flag release. Round-2 proven 64x128 tile, 4x8 microtile.
// ---------------------------------------------------------------------------
__global__ __launch_bounds__(256) void gemm_wx_kernel(
    const float* __restrict__ x,   // [BATCH*NF, WIN]
    const float* __restrict__ Wn,  // [WIN, EMB]
    const float* __restrict__ bn,  // [EMB]
    const float* __restrict__ a)   // [2*EMB]
{
#if __CUDA_ARCH__ >= 900
    if (threadIdx.x == 0) cudaTriggerProgrammaticLaunchCompletion();
#endif
    __shared__ float sX[32][65];    // [k][m], padded
    __shared__ float sW[32][128];   // [k][e]

    const int t    = threadIdx.x;
    const int row0 = blockIdx.x * 64;
    const int tx   = t & 15;       // e-direction
    const int ty   = t >> 4;       // m-direction

    float acc[4][8];
#pragma unroll
    for (int i = 0; i < 4; i++)
#pragma unroll
        for (int j = 0; j < 8; j++) acc[i][j] = 0.0f;

    for (int kt = 0; kt < WIN; kt += 32) {
#pragma unroll
        for (int i = 0; i < 8; i++) {
            int idx = t + i * 256;
            int m = idx >> 5, w = idx & 31;
            sX[w][m] = x[(size_t)(row0 + m) * WIN + kt + w];
        }
#pragma unroll
        for (int i = 0; i < 16; i++) {
            int idx = t + i * 256;
            int kk = idx >> 7, e = idx & 127;
            sW[kk][e] = Wn[(size_t)(kt + kk) * EMB + e];
        }
        __syncthreads();

#pragma unroll
        for (int kk = 0; kk < 32; kk++) {
            float ra[4], rb[8];
#pragma unroll
            for (int i = 0; i < 4; i++) ra[i] = sX[kk][ty + 16 * i];
#pragma unroll
            for (int j = 0; j < 8; j++) rb[j] = sW[kk][tx + 16 * j];
#pragma unroll
            for (int i = 0; i < 4; i++)
#pragma unroll
                for (int j = 0; j < 8; j++)
                    acc[i][j] = fmaf(ra[i], rb[j], acc[i][j]);
        }
        __syncthreads();
    }

    // Epilogue: bias, store Wx, fused projections d1/d2
    float a1v[8], a2v[8], bnv[8];
#pragma unroll
    for (int j = 0; j < 8; j++) {
        int e = tx + 16 * j;
        a1v[j] = __ldg(a + e);
        a2v[j] = __ldg(a + EMB + e);
        bnv[j] = __ldg(bn + e);
    }
    float p1[4] = {0, 0, 0, 0};
    float p2[4] = {0, 0, 0, 0};
#pragma unroll
    for (int i = 0; i < 4; i++) {
        int m = row0 + ty + 16 * i;
#pragma unroll
        for (int j = 0; j < 8; j++) {
            int e = tx + 16 * j;
            float val = acc[i][j] + bnv[j];
            g_Wx[(size_t)m * EMB + e] = val;
            p1[i] = fmaf(val, a1v[j], p1[i]);
            p2[i] = fmaf(val, a2v[j], p2[i]);
        }
    }
#pragma unroll
    for (int i = 0; i < 4; i++) {
#pragma unroll
        for (int o = 8; o > 0; o >>= 1) {
            p1[i] += __shfl_xor_sync(0xffffffffu, p1[i], o);
            p2[i] += __shfl_xor_sync(0xffffffffu, p2[i], o);
        }
    }
    if (tx == 0) {
#pragma unroll
        for (int i = 0; i < 4; i++) {
            int m = row0 + ty + 16 * i;
            g_d1[m] = p1[i];
            g_d2[m] = p2[i];
        }
    }

    // Release this tile: batch = rows/256 = bid/4
    __syncthreads();
    if (t == 0) {
        __threadfence();
        atomicAdd(&g_flag[blockIdx.x >> 2], 1u);
    }
}

// ---------------------------------------------------------------------------
// Kernel 2 (PDL secondary): warp-autonomous attention + streaming output.
// Spins on per-batch flag (fine-grained dependency on the primary), then
// one warp per (b,n): scores -> warp softmax -> 32 x (LDG.128, lrelu*att,
// STG.128 streaming). Self-resets flags for graph replay.
// ---------------------------------------------------------------------------
__global__ __launch_bounds__(256) void attn_stream_kernel(
    const int*   __restrict__ edge,   // [2, NF*TOPK] (row 0 used)
    const float* __restrict__ bias,   // [NF, TOPK]
    float*       __restrict__ out)    // [BATCH, NF, TOPK, EMB]
{
    const int t   = threadIdx.x;
    const int bid = blockIdx.x;
    const int wid = t >> 5;
    const int l   = t & 31;
    const int gw  = bid * 8 + wid;    // (b,n) pair; all 8 warps share b
    const int b   = gw >> 8;          // NF = 256
    const int n   = gw & 255;

    // Wait for batch b's 4 GEMM tiles
    if (t == 0) {
        volatile unsigned* f = &g_flag[b];
        while (*f < 4u) { }
        __threadfence();               // acquire
    }
    __syncthreads();

    const float* d1 = g_d1 + b * NF;
    const float* d2 = g_d2 + b * NF;

    const int nbr_l = __ldg(edge + n * TOPK + l);

    float score;
    if (l < 16) {
        score = lrelu(d1[n] + d2[n]);
    } else {
        int j0 = 2 * l - 32;
        int n0 = __ldg(edge + n * TOPK + j0);
        int n1 = __ldg(edge + n * TOPK + j0 + 1);
        score = lrelu(d1[n0] + d2[n1]);
    }
    float bv = __ldg(bias + n * TOPK + l);
    if (isnan(bv)) bv = 0.0f;
    else if (isinf(bv)) bv = bv > 0.0f ? 3.4028235e38f : -3.4028235e38f;
    score += bv;

    // Warp softmax over 32 lanes
    float m = score;
#pragma unroll
    for (int o = 16; o > 0; o >>= 1) m = fmaxf(m, __shfl_xor_sync(0xffffffffu, m, o));
    float ex = __expf(score - m);
    float s = ex;
#pragma unroll
    for (int o = 16; o > 0; o >>= 1) s += __shfl_xor_sync(0xffffffffu, s, o);
    const float att = ex / s;

    // Streaming output: 32 rows x 32 float4
    const float* wxb = g_Wx + (size_t)b * NF * EMB;
    float4* outp = (float4*)(out + (size_t)gw * TOPK * EMB);

#pragma unroll 8
    for (int k = 0; k < TOPK; k++) {
        int   nb = __shfl_sync(0xffffffffu, nbr_l, k);
        float ak = __shfl_sync(0xffffffffu, att,   k);
        const float4* src = (const float4*)(wxb + (size_t)nb * EMB);
        float4 v = __ldcg(src + l);
        v.x = lrelu(v.x) * ak;
        v.y = lrelu(v.y) * ak;
        v.z = lrelu(v.z) * ak;
        v.w = lrelu(v.w) * ak;
        __stcs(outp + k * 32 + l, v);
    }

    // Self-reset for graph replay: last attn block clears flags + counter.
    __syncthreads();
    if (t == 0) {
        unsigned v = atomicAdd(&g_done, 1u);
        if (v == (unsigned)(ATTN_BLK - 1)) {
#pragma unroll
            for (int i = 0; i < BATCH; i++) g_flag[i] = 0u;
            g_done = 0u;
            __threadfence();
        }
    }
}

// ---------------------------------------------------------------------------
// Launch. GEMM is the PDL primary; attn is launched with programmatic
// stream serialization so it overlaps the GEMM (fine sync via g_flag).
// Inputs: 0:x_n 1:x_e 2:edge 3:all_embeddings 4:W_n 5:b_n 6:a 7:bias_n
// ---------------------------------------------------------------------------
extern "C" void kernel_launch(void* const* d_in, const int* in_sizes, int n_in,
                              void* d_out, int out_size) {
    const float* x_n  = (const float*)d_in[0];
    const int*   edge = (const int*)  d_in[2];
    const float* W_n  = (const float*)d_in[4];
    const float* b_n  = (const float*)d_in[5];
    const float* a    = (const float*)d_in[6];
    const float* bias = (const float*)d_in[7];
    float* out = (float*)d_out;

    gemm_wx_kernel<<<GEMM_BLK, 256>>>(x_n, W_n, b_n, a);

    cudaLaunchAttribute attrs[1];
    attrs[0].id = cudaLaunchAttributeProgrammaticStreamSerialization;
    attrs[0].val.programmaticStreamSerializationAllowed = 1;

    cudaLaunchConfig_t cfg = {};
    cfg.gridDim  = dim3(ATTN_BLK, 1, 1);
    cfg.blockDim = dim3(256, 1, 1);
    cfg.dynamicSmemBytes = 0;
    cfg.stream   = 0;            // legacy default stream (same as <<<>>>)
    cfg.attrs    = attrs;
    cfg.numAttrs = 1;

    cudaError_t e = cudaLaunchKernelEx(&cfg, attn_stream_kernel, edge, bias, out);
    if (e != cudaSuccess) {
        // Fallback: plain serialized launch (still correct)
        attn_stream_kernel<<<ATTN_BLK, 256>>>(edge, bias, out);
    }
}

// round 6
// speedup vs baseline: 1.1911x; 1.0604x over previous
#include <cuda_runtime.h>
#include <cuda_bf16.h>
#include <math.h>

// Problem constants
#define BATCH   64
#define NF      256
#define WIN     128
#define EMB     128
#define TOPK    32
#define ALPHA   0.2f

// Scratch
__device__ float g_Wx[BATCH * NF * EMB];   // Wx = x_n @ W_n + b_n  (8.4 MB)
__device__ float g_d1[BATCH * NF];         // dot(Wx[b,r], a[:128])
__device__ float g_d2[BATCH * NF];         // dot(Wx[b,r], a[128:])

__device__ __forceinline__ float lrelu(float v) {
    return fmaxf(v, ALPHA * v);   // valid for alpha in (0,1)
}

// ---------------------------------------------------------------------------
// Kernel 1: GEMM  Wx[r][e] = sum_w x[r][w]*W[w][e] + b[e], fused d1/d2.
// Round-2 proven config: 256 blocks x 64 rows, 256 thr, 4x8 microtile (~17us,
// ~86% of fp32 FMA peak -- at its non-tensor floor).
// ---------------------------------------------------------------------------
__global__ __launch_bounds__(256) void gemm_wx_kernel(
    const float* __restrict__ x,   // [BATCH*NF, WIN]
    const float* __restrict__ Wn,  // [WIN, EMB]
    const float* __restrict__ bn,  // [EMB]
    const float* __restrict__ a)   // [2*EMB]
{
    __shared__ float sX[32][65];    // [k][m], padded
    __shared__ float sW[32][128];   // [k][e]

    const int t    = threadIdx.x;
    const int row0 = blockIdx.x * 64;
    const int tx   = t & 15;       // e-direction
    const int ty   = t >> 4;       // m-direction

    float acc[4][8];
#pragma unroll
    for (int i = 0; i < 4; i++)
#pragma unroll
        for (int j = 0; j < 8; j++) acc[i][j] = 0.0f;

    for (int kt = 0; kt < WIN; kt += 32) {
#pragma unroll
        for (int i = 0; i < 8; i++) {
            int idx = t + i * 256;
            int m = idx >> 5, w = idx & 31;
            sX[w][m] = x[(size_t)(row0 + m) * WIN + kt + w];
        }
#pragma unroll
        for (int i = 0; i < 16; i++) {
            int idx = t + i * 256;
            int kk = idx >> 7, e = idx & 127;
            sW[kk][e] = Wn[(size_t)(kt + kk) * EMB + e];
        }
        __syncthreads();

#pragma unroll
        for (int kk = 0; kk < 32; kk++) {
            float ra[4], rb[8];
#pragma unroll
            for (int i = 0; i < 4; i++) ra[i] = sX[kk][ty + 16 * i];
#pragma unroll
            for (int j = 0; j < 8; j++) rb[j] = sW[kk][tx + 16 * j];
#pragma unroll
            for (int i = 0; i < 4; i++)
#pragma unroll
                for (int j = 0; j < 8; j++)
                    acc[i][j] = fmaf(ra[i], rb[j], acc[i][j]);
        }
        __syncthreads();
    }

    // Epilogue: bias, store Wx, fused projections d1/d2
    float a1v[8], a2v[8], bnv[8];
#pragma unroll
    for (int j = 0; j < 8; j++) {
        int e = tx + 16 * j;
        a1v[j] = __ldg(a + e);
        a2v[j] = __ldg(a + EMB + e);
        bnv[j] = __ldg(bn + e);
    }
    float p1[4] = {0, 0, 0, 0};
    float p2[4] = {0, 0, 0, 0};
#pragma unroll
    for (int i = 0; i < 4; i++) {
        int m = row0 + ty + 16 * i;
#pragma unroll
        for (int j = 0; j < 8; j++) {
            int e = tx + 16 * j;
            float val = acc[i][j] + bnv[j];
            g_Wx[(size_t)m * EMB + e] = val;
            p1[i] = fmaf(val, a1v[j], p1[i]);
            p2[i] = fmaf(val, a2v[j], p2[i]);
        }
    }
#pragma unroll
    for (int i = 0; i < 4; i++) {
#pragma unroll
        for (int o = 8; o > 0; o >>= 1) {
            p1[i] += __shfl_xor_sync(0xffffffffu, p1[i], o);
            p2[i] += __shfl_xor_sync(0xffffffffu, p2[i], o);
        }
    }
    if (tx == 0) {
#pragma unroll
        for (int i = 0; i < 4; i++) {
            int m = row0 + ty + 16 * i;
            g_d1[m] = p1[i];
            g_d2[m] = p2[i];
        }
    }
}

// ---------------------------------------------------------------------------
// Kernel 2: batch-affine attention + streaming output.
// 128 blocks x 1024 threads: block = half-batch (128 n's of ONE batch b).
// One block per SM -> the batch's Wx slice (128 KB) stays resident in L1,
// so the 32 gather reads per (b,n) become L1 hits instead of L2 traffic
// (we were at the ~12 TB/s LTS cap; this halves LTS bytes).
// Warp w, round r handles n = half*128 + r*32 + w. No syncs needed.
// ---------------------------------------------------------------------------
__global__ __launch_bounds__(1024) void attn_stream_kernel(
    const int*   __restrict__ edge,   // [2, NF*TOPK] (row 0 used)
    const float* __restrict__ bias,   // [NF, TOPK]
    float*       __restrict__ out)    // [BATCH, NF, TOPK, EMB]
{
    const int t    = threadIdx.x;
    const int w    = t >> 5;          // warp 0..31
    const int l    = t & 31;
    const int b    = blockIdx.x >> 1;         // batch
    const int half = blockIdx.x & 1;          // which 128 n's

    const float* d1  = g_d1 + b * NF;
    const float* d2  = g_d2 + b * NF;
    const float* wxb = g_Wx + (size_t)b * NF * EMB;

#pragma unroll 1
    for (int r = 0; r < 4; r++) {
        const int n  = half * 128 + r * 32 + w;
        const int gw = b * NF + n;

        const int nbr_l = __ldg(edge + n * TOPK + l);

        // Score for lane l
        float score;
        if (l < 16) {
            score = lrelu(d1[n] + d2[n]);
        } else {
            int j0 = 2 * l - 32;
            int n0 = __ldg(edge + n * TOPK + j0);
            int n1 = __ldg(edge + n * TOPK + j0 + 1);
            score = lrelu(d1[n0] + d2[n1]);
        }
        float bv = __ldg(bias + n * TOPK + l);
        if (isnan(bv)) bv = 0.0f;
        else if (isinf(bv)) bv = bv > 0.0f ? 3.4028235e38f : -3.4028235e38f;
        score += bv;

        // Warp softmax over 32 lanes
        float m = score;
#pragma unroll
        for (int o = 16; o > 0; o >>= 1) m = fmaxf(m, __shfl_xor_sync(0xffffffffu, m, o));
        float ex = __expf(score - m);
        float s = ex;
#pragma unroll
        for (int o = 16; o > 0; o >>= 1) s += __shfl_xor_sync(0xffffffffu, s, o);
        const float att = ex / s;

        // Streaming output: 32 rows x 32 float4. Gathers via __ldg (L1-cached,
        // batch slice is L1-resident); stores streamed past L1/L2.
        float4* outp = (float4*)(out + (size_t)gw * TOPK * EMB);

#pragma unroll 8
        for (int k = 0; k < TOPK; k++) {
            int   nb = __shfl_sync(0xffffffffu, nbr_l, k);
            float ak = __shfl_sync(0xffffffffu, att,   k);
            const float4* src = (const float4*)(wxb + (size_t)nb * EMB);
            float4 v = __ldg(src + l);
            v.x = lrelu(v.x) * ak;
            v.y = lrelu(v.y) * ak;
            v.z = lrelu(v.z) * ak;
            v.w = lrelu(v.w) * ak;
            __stcs(outp + k * 32 + l, v);
        }
    }
}

// ---------------------------------------------------------------------------
// Launch. Inputs: 0:x_n 1:x_e 2:edge_indices 3:all_embeddings 4:W_n 5:b_n
//                 6:a 7:bias_n   (x_e, all_embeddings unused)
// ---------------------------------------------------------------------------
extern "C" void kernel_launch(void* const* d_in, const int* in_sizes, int n_in,
                              void* d_out, int out_size) {
    const float* x_n  = (const float*)d_in[0];
    const int*   edge = (const int*)  d_in[2];
    const float* W_n  = (const float*)d_in[4];
    const float* b_n  = (const float*)d_in[5];
    const float* a    = (const float*)d_in[6];
    const float* bias = (const float*)d_in[7];
    float* out = (float*)d_out;

    gemm_wx_kernel<<<(BATCH * NF) / 64, 256>>>(x_n, W_n, b_n, a);
    attn_stream_kernel<<<BATCH * 2, 1024>>>(edge, bias, out);
}